// round 4
// baseline (speedup 1.0000x reference)
#include <cuda_runtime.h>

#define BATCH 256
#define TT    512
#define INSZ  256
#define HID   512
#define NG    2048          // 4*HID, gate-interleaved columns: n = h*4 + gate (0=i,1=f,2=g,3=o)
#define KTOT  768           // INSZ + HID, concatenated K
#define NC    128

// ---------------- scratch (__device__ globals; total ~8 MB) ----------------
__device__ float g_W2[KTOT * NG];        // [k][n]: rows 0..255 = Wih^T, 256..767 = Whh^T (gate-interleaved)
__device__ float g_bias[NG];             // b_ih + b_hh, gate-interleaved
__device__ float g_Wfct[HID * NC];       // [h][j] transposed FC weight
__device__ float g_h[2][BATCH * HID];    // double-buffered hidden state
__device__ float g_c[BATCH * HID];       // cell state

__device__ __forceinline__ float sigm_f(float x) { return 1.f / (1.f + __expf(-x)); }
__device__ __forceinline__ float tanh_f(float x) { return 1.f - 2.f / (__expf(2.f * x) + 1.f); }

// ---------------- init: zero h0 and c0 (must be inside the graph: replays re-run it) ----------------
__global__ void init_kernel() {
    int i = blockIdx.x * blockDim.x + threadIdx.x;
    if (i < BATCH * HID) { g_h[0][i] = 0.f; g_c[i] = 0.f; }
}

// ---------------- weight reorder: transpose + gate-interleave + concat ----------------
__global__ void reorder_kernel(const float* __restrict__ Wih, const float* __restrict__ Whh,
                               const float* __restrict__ bih, const float* __restrict__ bhh,
                               const float* __restrict__ Wfc) {
    int idx = blockIdx.x * blockDim.x + threadIdx.x;
    const int T1 = KTOT * NG;           // g_W2
    const int T2 = T1 + NG;             // bias
    const int T3 = T2 + HID * NC;       // Wfc_t
    if (idx < T1) {
        int k = idx / NG, n = idx % NG;
        int gate = n & 3, h = n >> 2;
        int row = gate * HID + h;
        g_W2[idx] = (k < INSZ) ? Wih[row * INSZ + k] : Whh[row * HID + (k - INSZ)];
    } else if (idx < T2) {
        int n = idx - T1;
        int gate = n & 3, h = n >> 2;
        g_bias[n] = bih[gate * HID + h] + bhh[gate * HID + h];
    } else if (idx < T3) {
        int j = idx - T2;
        int h = j / NC, c = j % NC;
        g_Wfct[j] = Wfc[c * HID + h];
    }
}

// ---------------- one LSTM timestep ----------------
// gates[256, 2048] = [x_t | h_prev] @ g_W2 + bias, then fused cell update.
// Grid: (32 n-tiles) x (4 m-tiles) = 128 blocks, 256 threads, 64x64 tile, 4x4/thread.
// Thread (tx,ty) owns gate columns n0+tx*4..+3 == the 4 gates of hidden unit hidx,
// for batch rows m0+ty*4..+3  ->  cell update is a pure epilogue; c in g_c.
__global__ __launch_bounds__(256) void step_kernel(const float* __restrict__ x, int t) {
    __shared__ float As[16][64];
    __shared__ float Bs[16][64];
    const int tid = threadIdx.x;
    const int tx = tid & 15, ty = tid >> 4;
    const int n0 = blockIdx.x * 64;
    const int m0 = blockIdx.y * 64;
    const int r = tid >> 2, kg = tid & 3;        // A-tile loader: row r, 4-float group kg
    const int hidx = (n0 >> 2) + tx;

    const float* __restrict__ hc = g_h[t & 1];
    float* __restrict__ hn = g_h[(t & 1) ^ 1];
    const float* xrow = &x[((size_t)(m0 + r) * TT + t) * INSZ];

    float acc[4][4] = {};
    for (int kc = 0; kc < KTOT; kc += 16) {
        float4 av = (kc < INSZ)
            ? *(const float4*)&xrow[kc + kg * 4]
            : *(const float4*)&hc[(m0 + r) * HID + (kc - INSZ) + kg * 4];
        As[kg * 4 + 0][r] = av.x; As[kg * 4 + 1][r] = av.y;
        As[kg * 4 + 2][r] = av.z; As[kg * 4 + 3][r] = av.w;
        *(float4*)&Bs[ty][tx * 4] = *(const float4*)&g_W2[(kc + ty) * NG + n0 + tx * 4];
        __syncthreads();
#pragma unroll
        for (int k = 0; k < 16; k++) {
            float4 aa = *(const float4*)&As[k][ty * 4];
            float4 bb = *(const float4*)&Bs[k][tx * 4];
            acc[0][0] += aa.x * bb.x; acc[0][1] += aa.x * bb.y; acc[0][2] += aa.x * bb.z; acc[0][3] += aa.x * bb.w;
            acc[1][0] += aa.y * bb.x; acc[1][1] += aa.y * bb.y; acc[1][2] += aa.y * bb.z; acc[1][3] += aa.y * bb.w;
            acc[2][0] += aa.z * bb.x; acc[2][1] += aa.z * bb.y; acc[2][2] += aa.z * bb.z; acc[2][3] += aa.z * bb.w;
            acc[3][0] += aa.w * bb.x; acc[3][1] += aa.w * bb.y; acc[3][2] += aa.w * bb.z; acc[3][3] += aa.w * bb.w;
        }
        __syncthreads();
    }

    float4 bias4 = *(const float4*)&g_bias[n0 + tx * 4];
#pragma unroll
    for (int i = 0; i < 4; i++) {
        int b = m0 + ty * 4 + i;
        float gi = acc[i][0] + bias4.x;
        float gf = acc[i][1] + bias4.y;
        float gg = acc[i][2] + bias4.z;
        float go = acc[i][3] + bias4.w;
        float c = sigm_f(gf) * g_c[b * HID + hidx] + sigm_f(gi) * tanh_f(gg);
        g_c[b * HID + hidx] = c;
        hn[b * HID + hidx] = sigm_f(go) * tanh_f(c);
    }
}

// ---------------- FC head: out = h_last @ Wfc^T + b_fc ----------------
__global__ __launch_bounds__(128) void fc_kernel(const float* __restrict__ bfc, float* __restrict__ out) {
    __shared__ float hs[HID];
    const int b = blockIdx.x;
    for (int i = threadIdx.x; i < HID; i += blockDim.x)
        hs[i] = g_h[0][b * HID + i];          // TT even -> final h lands in buffer 0
    __syncthreads();
    const int j = threadIdx.x;
    float s = bfc[j];
#pragma unroll 8
    for (int h = 0; h < HID; h++)
        s += hs[h] * g_Wfct[h * NC + j];
    out[b * NC + j] = s;
}

// ---------------- launch ----------------
extern "C" void kernel_launch(void* const* d_in, const int* in_sizes, int n_in,
                              void* d_out, int out_size) {
    const float* x   = (const float*)d_in[0];
    const float* Wih = (const float*)d_in[1];
    const float* Whh = (const float*)d_in[2];
    const float* bih = (const float*)d_in[3];
    const float* bhh = (const float*)d_in[4];
    const float* Wfc = (const float*)d_in[5];
    const float* bfc = (const float*)d_in[6];
    float* out = (float*)d_out;

    init_kernel<<<(BATCH * HID + 255) / 256, 256>>>();

    const int reorder_total = KTOT * NG + NG + HID * NC;
    reorder_kernel<<<(reorder_total + 255) / 256, 256>>>(Wih, Whh, bih, bhh, Wfc);

    dim3 gs(NG / 64, BATCH / 64);   // (32, 4) = 128 blocks
    for (int t = 0; t < TT; t++)
        step_kernel<<<gs, 256>>>(x, t);

    fc_kernel<<<BATCH, NC>>>(bfc, out);
}